// round 4
// baseline (speedup 1.0000x reference)
#include <cuda_runtime.h>

#define NP   16     // B*K problems
#define N    2048   // points per cloud
#define JC1  8      // j-chunks, chain 1 (CP=4)
#define JCH1 (N / JC1)
#define JC2  8      // j-chunks, chain 2 (CP=12)
#define JCH2 (N / JC2)

// ---------------- scratch (__device__ globals: allocation-free) ----------------
__device__ float4 g_Xs[NP][N];                  // scaled points + squared norm
__device__ float  g_deg[NP][N];                 // row degree of thresholded W
__device__ float  g_PT[NP][N][N];               // PT[p][j][i] = P[i][j] (transposed)
__device__ float  g_F[NP][N * 4];               // chain-1 t=0 (x,y,z,0)
__device__ float  g_U[NP][N * 12];              // chain-2 t=0 (first 12 cols of U)
__device__ float  g_p1[17][JC1][NP][N * 4];     // chain-1 per-step j-chunk partials
__device__ float  g_p2[17][JC2][NP][N * 12];    // chain-2 per-step j-chunk partials

// ---------------- helpers ----------------
__device__ __forceinline__ unsigned long long pack2(float a) {
    unsigned long long r;
    asm("mov.b64 %0, {%1, %1};" : "=l"(r) : "f"(a));
    return r;
}
__device__ __forceinline__ void fma2(unsigned long long& d, unsigned long long a,
                                     unsigned long long b) {
    asm("fma.rn.f32x2 %0, %1, %2, %0;" : "+l"(d) : "l"(a), "l"(b));
}
__device__ __forceinline__ float2 unpk(unsigned long long v) {
    float2 r;
    asm("mov.b64 {%0, %1}, %2;" : "=f"(r.x), "=f"(r.y) : "l"(v));
    return r;
}
__device__ __forceinline__ float warpSum(float v) {
#pragma unroll
    for (int o = 16; o; o >>= 1) v += __shfl_xor_sync(0xffffffffu, v, o);
    return v;
}

// ---------------- 1. scale points, init chain-1 state ----------------
__global__ void prepK(const float* __restrict__ pc, const float* __restrict__ al) {
    int idx = blockIdx.x * blockDim.x + threadIdx.x;
    if (idx >= NP * N) return;
    int p = idx / N, i = idx - p * N;
    int b = p >> 2, k = p & 3;
    const float* xp = pc + ((size_t)b * N + i) * 3;
    float x = xp[0] * al[k * 3 + 0];
    float y = xp[1] * al[k * 3 + 1];
    float z = xp[2] * al[k * 3 + 2];
    g_Xs[p][i] = make_float4(x, y, z, x * x + y * y + z * z);
    ((float4*)&g_F[p][0])[i] = make_float4(x, y, z, 0.f);
}

// ---------------- 2. degrees (row sums of thresholded W) ----------------
__global__ void degK() {
    int r = blockIdx.x * 8 + (threadIdx.x >> 5);   // one warp per row
    int lane = threadIdx.x & 31;
    int p = r / N, i = r - p * N;
    float4 xi = g_Xs[p][i];
    float s = 0.f;
    for (int j = lane; j < N; j += 32) {
        float4 xj = g_Xs[p][j];
        float d = xi.w + xj.w - 2.f * (xi.x * xj.x + xi.y * xj.y + xi.z * xj.z);
        float w = __expf(-d * 0.1f);
        s += (w < 0.1f) ? 0.f : w;
    }
    s = warpSum(s);
    if (lane == 0) g_deg[p][i] = s;
}

// ---------------- 3. build transposed lazy-walk matrix ----------------
__global__ void buildK() {
    int p = blockIdx.z;
    int i = blockIdx.x * 256 + threadIdx.x;
    int j0 = blockIdx.y * 8;
    float4 xi = g_Xs[p][i];
    float rd = 0.5f / g_deg[p][i];
#pragma unroll
    for (int jj = 0; jj < 8; jj++) {
        int j = j0 + jj;
        float4 xj = g_Xs[p][j];
        float d = xi.w + xj.w - 2.f * (xi.x * xj.x + xi.y * xj.y + xi.z * xj.z);
        float w = __expf(-d * 0.1f);
        w = (w < 0.1f) ? 0.f : w;
        g_PT[p][j][i] = w * rd + ((i == j) ? 0.5f : 0.f);
    }
}

// ---------------- 4a. chain-1 apply: partial(next) over a j-chunk (CP=4) --------
// R2-proven shape: 2 rows/thread, float2 P loads, unroll 8. Staging fuses the
// reduce of the previous step's JC1 partials (fixed order => deterministic).
// Plain (caching) loads: P is meant to be L2-resident within a problem group.
__global__ void __launch_bounds__(128) apply1K(int sSrc, int sDst, int p0) {
    __shared__ __align__(16) float sc[JCH1 * 4];
    int p  = p0 + blockIdx.z;
    int jb = blockIdx.y * JCH1;
    int i0 = blockIdx.x * 256 + threadIdx.x * 2;

    for (int t = threadIdx.x; t < JCH1; t += 128) {
        float4 s;
        if (sSrc == 0) {
            s = ((const float4*)&g_F[p][0])[jb + t];
        } else {
            s = make_float4(0.f, 0.f, 0.f, 0.f);
#pragma unroll
            for (int jc = 0; jc < JC1; jc++) {
                float4 v = ((const float4*)&g_p1[sSrc][jc][p][0])[jb + t];
                s.x += v.x; s.y += v.y; s.z += v.z; s.w += v.w;
            }
        }
        ((float4*)sc)[t] = s;
    }
    __syncthreads();

    const float* PTp = &g_PT[p][0][0] + (size_t)jb * N;
    unsigned long long a0[2], a1[2];
    a0[0] = a0[1] = a1[0] = a1[1] = 0ull;

#pragma unroll 8
    for (int j = 0; j < JCH1; j++) {
        float2 pv = *(const float2*)(PTp + (size_t)j * N + i0);
        unsigned long long px = pack2(pv.x), py = pack2(pv.y);
        const unsigned long long* cs = (const unsigned long long*)(sc + j * 4);
        unsigned long long c0 = cs[0], c1 = cs[1];
        fma2(a0[0], px, c0); fma2(a0[1], px, c1);
        fma2(a1[0], py, c0); fma2(a1[1], py, c1);
    }

    float4* o = (float4*)(&g_p1[sDst][blockIdx.y][p][0] + (size_t)i0 * 4);
    {
        float2 lo = unpk(a0[0]), hi = unpk(a0[1]);
        o[0] = make_float4(lo.x, lo.y, hi.x, hi.y);
        float2 lo1 = unpk(a1[0]), hi1 = unpk(a1[1]);
        o[1] = make_float4(lo1.x, lo1.y, hi1.x, hi1.y);
    }
}

// ---------------- 4b. chain-2 apply: partial(next) over a j-chunk (CP=12) -------
__global__ void __launch_bounds__(128) apply2K(int sSrc, int sDst, int p0) {
    __shared__ __align__(16) float sc[JCH2 * 12];        // 12 KB
    int p  = p0 + blockIdx.z;
    int jb = blockIdx.y * JCH2;
    int i0 = blockIdx.x * 256 + threadIdx.x * 2;

    for (int t = threadIdx.x; t < JCH2 * 12 / 4; t += 128) {
        float4 s;
        if (sSrc == 0) {
            s = ((const float4*)&g_U[p][0])[jb * 3 + t];
        } else {
            s = make_float4(0.f, 0.f, 0.f, 0.f);
#pragma unroll
            for (int jc = 0; jc < JC2; jc++) {
                float4 v = ((const float4*)&g_p2[sSrc][jc][p][0])[jb * 3 + t];
                s.x += v.x; s.y += v.y; s.z += v.z; s.w += v.w;
            }
        }
        ((float4*)sc)[t] = s;
    }
    __syncthreads();

    const float* PTp = &g_PT[p][0][0] + (size_t)jb * N;
    unsigned long long a0[6], a1[6];
#pragma unroll
    for (int c = 0; c < 6; c++) { a0[c] = 0ull; a1[c] = 0ull; }

#pragma unroll 8
    for (int j = 0; j < JCH2; j++) {
        float2 pv = *(const float2*)(PTp + (size_t)j * N + i0);
        unsigned long long px = pack2(pv.x), py = pack2(pv.y);
        const unsigned long long* cs = (const unsigned long long*)(sc + j * 12);
#pragma unroll
        for (int c = 0; c < 6; c++) {
            unsigned long long cv = cs[c];
            fma2(a0[c], px, cv);
            fma2(a1[c], py, cv);
        }
    }

    float4* o = (float4*)(&g_p2[sDst][blockIdx.y][p][0] + (size_t)i0 * 12);
#pragma unroll
    for (int q = 0; q < 3; q++) {
        float2 e0 = unpk(a0[2 * q]), e1 = unpk(a0[2 * q + 1]);
        o[q] = make_float4(e0.x, e0.y, e1.x, e1.y);
    }
#pragma unroll
    for (int q = 0; q < 3; q++) {
        float2 e0 = unpk(a1[2 * q]), e1 = unpk(a1[2 * q + 1]);
        o[3 + q] = make_float4(e0.x, e0.y, e1.x, e1.y);
    }
}

// ---------------- 5. first-order features + build U + partial output ----------------
__global__ void midK(float* __restrict__ out, int p0) {
    int p = p0 + blockIdx.x, tid = threadIdx.x;
    const int slots[5] = {1, 2, 4, 8, 16};
    float ls[18];
#pragma unroll
    for (int v = 0; v < 18; v++) ls[v] = 0.f;

    for (int i = tid; i < N; i += 256) {
        float L[6][3];
        {
            float4 f0 = ((const float4*)&g_F[p][0])[i];
            L[0][0] = f0.x; L[0][1] = f0.y; L[0][2] = f0.z;
        }
#pragma unroll
        for (int s = 0; s < 5; s++) {
            float4 acc = make_float4(0.f, 0.f, 0.f, 0.f);
#pragma unroll
            for (int jc = 0; jc < JC1; jc++) {
                float4 v = ((const float4*)&g_p1[slots[s]][jc][p][0])[i];
                acc.x += v.x; acc.y += v.y; acc.z += v.z;
            }
            L[s + 1][0] = acc.x; L[s + 1][1] = acc.y; L[s + 1][2] = acc.z;
        }
        float* U = &g_U[p][i * 12];
#pragma unroll
        for (int c = 0; c < 3; c++) {
            float u0 = fabsf(L[0][c] - L[1][c]);
            float u1 = fabsf(L[1][c] - L[2][c]);
            float u2 = fabsf(L[2][c] - L[3][c]);
            float u3 = fabsf(L[3][c] - L[4][c]);
            float u4 = fabsf(L[4][c] - L[5][c]);
            U[c] = u0; U[3 + c] = u1; U[6 + c] = u2; U[9 + c] = u3;
            ls[c]      += L[5][c];
            ls[3 + c]  += u0;  ls[6 + c]  += u1;  ls[9 + c]  += u2;
            ls[12 + c] += u3;  ls[15 + c] += u4;
        }
    }
    __shared__ float red[18][8];
    int wid = tid >> 5, lane = tid & 31;
#pragma unroll
    for (int v = 0; v < 18; v++) {
        float s = warpSum(ls[v]);
        if (lane == 0) red[v][wid] = s;
    }
    __syncthreads();
    if (tid < 18) {
        float s = 0.f;
#pragma unroll
        for (int w = 0; w < 8; w++) s += red[tid][w];
        int b = p >> 2, k = p & 3;
        out[b * 192 + k * 48 + tid] = s * (1.f / 2048.f);
    }
}

// ---------------- 6. second-order features + remaining output ----------------
__global__ void finalK(float* __restrict__ out) {
    int p = blockIdx.x, tid = threadIdx.x;
    const int slots[5] = {1, 2, 4, 8, 16};
    float ls[30];
#pragma unroll
    for (int v = 0; v < 30; v++) ls[v] = 0.f;

    for (int i = tid; i < N; i += 256) {
        float A[5][12];
#pragma unroll
        for (int s = 0; s < 5; s++) {
#pragma unroll
            for (int q = 0; q < 3; q++) {
                float4 acc = make_float4(0.f, 0.f, 0.f, 0.f);
#pragma unroll
                for (int jc = 0; jc < JC2; jc++) {
                    float4 v = ((const float4*)&g_p2[slots[s]][jc][p][0])[i * 3 + q];
                    acc.x += v.x; acc.y += v.y; acc.z += v.z; acc.w += v.w;
                }
                A[s][4 * q + 0] = acc.x; A[s][4 * q + 1] = acc.y;
                A[s][4 * q + 2] = acc.z; A[s][4 * q + 3] = acc.w;
            }
        }
#pragma unroll
        for (int c = 0; c < 3;  c++) ls[c]      += fabsf(A[0][c] - A[1][c]);
#pragma unroll
        for (int c = 0; c < 6;  c++) ls[3 + c]  += fabsf(A[1][c] - A[2][c]);
#pragma unroll
        for (int c = 0; c < 9;  c++) ls[9 + c]  += fabsf(A[2][c] - A[3][c]);
#pragma unroll
        for (int c = 0; c < 12; c++) ls[18 + c] += fabsf(A[3][c] - A[4][c]);
    }
    __shared__ float red[30][8];
    int wid = tid >> 5, lane = tid & 31;
#pragma unroll
    for (int v = 0; v < 30; v++) {
        float s = warpSum(ls[v]);
        if (lane == 0) red[v][wid] = s;
    }
    __syncthreads();
    if (tid < 30) {
        float s = 0.f;
#pragma unroll
        for (int w = 0; w < 8; w++) s += red[tid][w];
        int b = p >> 2, k = p & 3;
        out[b * 192 + k * 48 + 18 + tid] = s * (1.f / 2048.f);
    }
}

// ---------------- launch ----------------
extern "C" void kernel_launch(void* const* d_in, const int* in_sizes, int n_in,
                              void* d_out, int out_size) {
    (void)in_sizes; (void)n_in; (void)out_size;
    const float* pc = (const float*)d_in[0];   // [4,2048,3]
    const float* al = (const float*)d_in[1];   // [4,3]
    float* out = (float*)d_out;                // [768]

    prepK<<<(NP * N + 255) / 256, 256>>>(pc, al);
    degK<<<NP * N / 8, 256>>>();
    buildK<<<dim3(N / 256, N / 8, NP), 256>>>();

    // L2-resident problem groups: P panels for the group stay hot across all
    // 32 chain steps of that group.
    const int gstart[4] = {0, 6, 11, 16};
    for (int g = 0; g < 3; g++) {
        int p0 = gstart[g];
        int gp = gstart[g + 1] - p0;
        for (int s = 1; s <= 16; s++)
            apply1K<<<dim3(8, JC1, gp), 128>>>(s - 1, s, p0);
        midK<<<gp, 256>>>(out, p0);
        for (int s = 1; s <= 16; s++)
            apply2K<<<dim3(8, JC2, gp), 128>>>(s - 1, s, p0);
    }

    finalK<<<NP, 256>>>(out);
}

// round 5
// speedup vs baseline: 2.0893x; 2.0893x over previous
#include <cuda_runtime.h>
#include <cuda_fp16.h>

#define NP   16     // B*K problems
#define N    2048   // points per cloud
#define JC1  8      // j-chunks, chain 1 (CP=4)
#define JCH1 (N / JC1)
#define JC2  8      // j-chunks, chain 2 (CP=12)
#define JCH2 (N / JC2)

// ---------------- scratch (__device__ globals: allocation-free) ----------------
__device__ float4 g_Xs[NP][N];                  // scaled points + squared norm
__device__ float  g_deg[NP][N];                 // row degree of thresholded W
__device__ __half g_PTh[NP][N][N];              // off-diag P, transposed: PTh[p][j][i]=P[i][j]; diag=0
__device__ float  g_dg[NP][N];                  // exact fp32 diagonal: 0.5 + 0.5/deg
__device__ float  g_F[NP][N * 4];               // chain-1 t=0 (x,y,z,0)
__device__ float  g_U[NP][N * 12];              // chain-2 t=0 (first 12 cols of U)
__device__ float  g_p1[17][JC1][NP][N * 4];     // chain-1 per-step j-chunk partials
__device__ float  g_p2[17][JC2][NP][N * 12];    // chain-2 per-step j-chunk partials

// ---------------- helpers ----------------
__device__ __forceinline__ unsigned long long pack2(float a) {
    unsigned long long r;
    asm("mov.b64 %0, {%1, %1};" : "=l"(r) : "f"(a));
    return r;
}
__device__ __forceinline__ void fma2(unsigned long long& d, unsigned long long a,
                                     unsigned long long b) {
    asm("fma.rn.f32x2 %0, %1, %2, %0;" : "+l"(d) : "l"(a), "l"(b));
}
__device__ __forceinline__ float2 unpk(unsigned long long v) {
    float2 r;
    asm("mov.b64 {%0, %1}, %2;" : "=f"(r.x), "=f"(r.y) : "l"(v));
    return r;
}
__device__ __forceinline__ float warpSum(float v) {
#pragma unroll
    for (int o = 16; o; o >>= 1) v += __shfl_xor_sync(0xffffffffu, v, o);
    return v;
}

// ---------------- 1. scale points, init chain-1 state ----------------
__global__ void prepK(const float* __restrict__ pc, const float* __restrict__ al) {
    int idx = blockIdx.x * blockDim.x + threadIdx.x;
    if (idx >= NP * N) return;
    int p = idx / N, i = idx - p * N;
    int b = p >> 2, k = p & 3;
    const float* xp = pc + ((size_t)b * N + i) * 3;
    float x = xp[0] * al[k * 3 + 0];
    float y = xp[1] * al[k * 3 + 1];
    float z = xp[2] * al[k * 3 + 2];
    g_Xs[p][i] = make_float4(x, y, z, x * x + y * y + z * z);
    ((float4*)&g_F[p][0])[i] = make_float4(x, y, z, 0.f);
}

// ---------------- 2. degrees (row sums of thresholded W) ----------------
__global__ void degK() {
    int r = blockIdx.x * 8 + (threadIdx.x >> 5);   // one warp per row
    int lane = threadIdx.x & 31;
    int p = r / N, i = r - p * N;
    float4 xi = g_Xs[p][i];
    float s = 0.f;
    for (int j = lane; j < N; j += 32) {
        float4 xj = g_Xs[p][j];
        float d = xi.w + xj.w - 2.f * (xi.x * xj.x + xi.y * xj.y + xi.z * xj.z);
        float w = __expf(-d * 0.1f);
        s += (w < 0.1f) ? 0.f : w;
    }
    s = warpSum(s);
    if (lane == 0) g_deg[p][i] = s;
}

// ---------------- 3. build transposed lazy-walk matrix (fp16 off-diag, fp32 diag) --
__global__ void buildK() {
    int p = blockIdx.z;
    int i = blockIdx.x * 256 + threadIdx.x;
    int j0 = blockIdx.y * 8;
    float4 xi = g_Xs[p][i];
    float rd = 0.5f / g_deg[p][i];
#pragma unroll
    for (int jj = 0; jj < 8; jj++) {
        int j = j0 + jj;
        float4 xj = g_Xs[p][j];
        float d = xi.w + xj.w - 2.f * (xi.x * xj.x + xi.y * xj.y + xi.z * xj.z);
        float w = __expf(-d * 0.1f);
        w = (w < 0.1f) ? 0.f : w;
        float v = (i == j) ? 0.f : w * rd;        // diag excluded, handled in fp32
        g_PTh[p][j][i] = __float2half_rn(v);
    }
    if (blockIdx.y == 0) g_dg[p][i] = 0.5f + rd;  // exact diag: 0.5*(1 + 1/deg)
}

// ---------------- 4a. chain-1 apply: partial(next) over a j-chunk (CP=4) --------
// R2-proven shape: 256 thr, 2 rows/thread, full 16-problem grid. P in fp16
// (converted to fp32 before FFMA2); exact diagonal added by the owning chunk.
// Staging fuses the reduce of the previous step's partials (fixed order).
__global__ void __launch_bounds__(256) apply1K(int sSrc, int sDst) {
    __shared__ __align__(16) float sc[JCH1 * 4];
    int p  = blockIdx.z;
    int jb = blockIdx.y * JCH1;
    int i0 = blockIdx.x * 512 + threadIdx.x * 2;

    for (int t = threadIdx.x; t < JCH1; t += 256) {
        float4 s;
        if (sSrc == 0) {
            s = ((const float4*)&g_F[p][0])[jb + t];
        } else {
            s = make_float4(0.f, 0.f, 0.f, 0.f);
#pragma unroll
            for (int jc = 0; jc < JC1; jc++) {
                float4 v = ((const float4*)&g_p1[sSrc][jc][p][0])[jb + t];
                s.x += v.x; s.y += v.y; s.z += v.z; s.w += v.w;
            }
        }
        ((float4*)sc)[t] = s;
    }
    __syncthreads();

    const __half* PTp = &g_PTh[p][0][0] + (size_t)jb * N;
    unsigned long long a0[2], a1[2];
    a0[0] = a0[1] = a1[0] = a1[1] = 0ull;

#pragma unroll 16
    for (int j = 0; j < JCH1; j++) {
        __half2 h = *(const __half2*)(PTp + (size_t)j * N + i0);
        float2 pv = __half22float2(h);
        unsigned long long px = pack2(pv.x), py = pack2(pv.y);
        const unsigned long long* cs = (const unsigned long long*)(sc + j * 4);
        unsigned long long c0 = cs[0], c1 = cs[1];
        fma2(a0[0], px, c0); fma2(a0[1], px, c1);
        fma2(a1[0], py, c0); fma2(a1[1], py, c1);
    }

    // exact fp32 diagonal: row i gets d_i * x_i (x staged in this chunk only)
    int jd = i0 - jb;
    if (jd >= 0 && jd < JCH1) {
        unsigned long long D0 = pack2(g_dg[p][i0]);
        unsigned long long D1 = pack2(g_dg[p][i0 + 1]);
        const unsigned long long* csd0 = (const unsigned long long*)(sc + jd * 4);
        const unsigned long long* csd1 = (const unsigned long long*)(sc + (jd + 1) * 4);
        fma2(a0[0], D0, csd0[0]); fma2(a0[1], D0, csd0[1]);
        fma2(a1[0], D1, csd1[0]); fma2(a1[1], D1, csd1[1]);
    }

    float4* o = (float4*)(&g_p1[sDst][blockIdx.y][p][0] + (size_t)i0 * 4);
    {
        float2 lo = unpk(a0[0]), hi = unpk(a0[1]);
        o[0] = make_float4(lo.x, lo.y, hi.x, hi.y);
        float2 lo1 = unpk(a1[0]), hi1 = unpk(a1[1]);
        o[1] = make_float4(lo1.x, lo1.y, hi1.x, hi1.y);
    }
}

// ---------------- 4b. chain-2 apply: partial(next) over a j-chunk (CP=12) -------
__global__ void __launch_bounds__(256) apply2K(int sSrc, int sDst) {
    __shared__ __align__(16) float sc[JCH2 * 12];        // 12 KB
    int p  = blockIdx.z;
    int jb = blockIdx.y * JCH2;
    int i0 = blockIdx.x * 512 + threadIdx.x * 2;

    for (int t = threadIdx.x; t < JCH2 * 12 / 4; t += 256) {
        float4 s;
        if (sSrc == 0) {
            s = ((const float4*)&g_U[p][0])[jb * 3 + t];
        } else {
            s = make_float4(0.f, 0.f, 0.f, 0.f);
#pragma unroll
            for (int jc = 0; jc < JC2; jc++) {
                float4 v = ((const float4*)&g_p2[sSrc][jc][p][0])[jb * 3 + t];
                s.x += v.x; s.y += v.y; s.z += v.z; s.w += v.w;
            }
        }
        ((float4*)sc)[t] = s;
    }
    __syncthreads();

    const __half* PTp = &g_PTh[p][0][0] + (size_t)jb * N;
    unsigned long long a0[6], a1[6];
#pragma unroll
    for (int c = 0; c < 6; c++) { a0[c] = 0ull; a1[c] = 0ull; }

#pragma unroll 8
    for (int j = 0; j < JCH2; j++) {
        __half2 h = *(const __half2*)(PTp + (size_t)j * N + i0);
        float2 pv = __half22float2(h);
        unsigned long long px = pack2(pv.x), py = pack2(pv.y);
        const unsigned long long* cs = (const unsigned long long*)(sc + j * 12);
#pragma unroll
        for (int c = 0; c < 6; c++) {
            unsigned long long cv = cs[c];
            fma2(a0[c], px, cv);
            fma2(a1[c], py, cv);
        }
    }

    // exact fp32 diagonal
    int jd = i0 - jb;
    if (jd >= 0 && jd < JCH2) {
        unsigned long long D0 = pack2(g_dg[p][i0]);
        unsigned long long D1 = pack2(g_dg[p][i0 + 1]);
        const unsigned long long* csd0 = (const unsigned long long*)(sc + jd * 12);
        const unsigned long long* csd1 = (const unsigned long long*)(sc + (jd + 1) * 12);
#pragma unroll
        for (int c = 0; c < 6; c++) {
            fma2(a0[c], D0, csd0[c]);
            fma2(a1[c], D1, csd1[c]);
        }
    }

    float4* o = (float4*)(&g_p2[sDst][blockIdx.y][p][0] + (size_t)i0 * 12);
#pragma unroll
    for (int q = 0; q < 3; q++) {
        float2 e0 = unpk(a0[2 * q]), e1 = unpk(a0[2 * q + 1]);
        o[q] = make_float4(e0.x, e0.y, e1.x, e1.y);
    }
#pragma unroll
    for (int q = 0; q < 3; q++) {
        float2 e0 = unpk(a1[2 * q]), e1 = unpk(a1[2 * q + 1]);
        o[3 + q] = make_float4(e0.x, e0.y, e1.x, e1.y);
    }
}

// ---------------- 5. first-order features + build U + partial output ----------------
__global__ void midK(float* __restrict__ out) {
    int p = blockIdx.x, tid = threadIdx.x;
    const int slots[5] = {1, 2, 4, 8, 16};
    float ls[18];
#pragma unroll
    for (int v = 0; v < 18; v++) ls[v] = 0.f;

    for (int i = tid; i < N; i += 256) {
        float L[6][3];
        {
            float4 f0 = ((const float4*)&g_F[p][0])[i];
            L[0][0] = f0.x; L[0][1] = f0.y; L[0][2] = f0.z;
        }
#pragma unroll
        for (int s = 0; s < 5; s++) {
            float4 acc = make_float4(0.f, 0.f, 0.f, 0.f);
#pragma unroll
            for (int jc = 0; jc < JC1; jc++) {
                float4 v = ((const float4*)&g_p1[slots[s]][jc][p][0])[i];
                acc.x += v.x; acc.y += v.y; acc.z += v.z;
            }
            L[s + 1][0] = acc.x; L[s + 1][1] = acc.y; L[s + 1][2] = acc.z;
        }
        float* U = &g_U[p][i * 12];
#pragma unroll
        for (int c = 0; c < 3; c++) {
            float u0 = fabsf(L[0][c] - L[1][c]);
            float u1 = fabsf(L[1][c] - L[2][c]);
            float u2 = fabsf(L[2][c] - L[3][c]);
            float u3 = fabsf(L[3][c] - L[4][c]);
            float u4 = fabsf(L[4][c] - L[5][c]);
            U[c] = u0; U[3 + c] = u1; U[6 + c] = u2; U[9 + c] = u3;
            ls[c]      += L[5][c];
            ls[3 + c]  += u0;  ls[6 + c]  += u1;  ls[9 + c]  += u2;
            ls[12 + c] += u3;  ls[15 + c] += u4;
        }
    }
    __shared__ float red[18][8];
    int wid = tid >> 5, lane = tid & 31;
#pragma unroll
    for (int v = 0; v < 18; v++) {
        float s = warpSum(ls[v]);
        if (lane == 0) red[v][wid] = s;
    }
    __syncthreads();
    if (tid < 18) {
        float s = 0.f;
#pragma unroll
        for (int w = 0; w < 8; w++) s += red[tid][w];
        int b = p >> 2, k = p & 3;
        out[b * 192 + k * 48 + tid] = s * (1.f / 2048.f);
    }
}

// ---------------- 6. second-order features + remaining output ----------------
__global__ void finalK(float* __restrict__ out) {
    int p = blockIdx.x, tid = threadIdx.x;
    const int slots[5] = {1, 2, 4, 8, 16};
    float ls[30];
#pragma unroll
    for (int v = 0; v < 30; v++) ls[v] = 0.f;

    for (int i = tid; i < N; i += 256) {
        float A[5][12];
#pragma unroll
        for (int s = 0; s < 5; s++) {
#pragma unroll
            for (int q = 0; q < 3; q++) {
                float4 acc = make_float4(0.f, 0.f, 0.f, 0.f);
#pragma unroll
                for (int jc = 0; jc < JC2; jc++) {
                    float4 v = ((const float4*)&g_p2[slots[s]][jc][p][0])[i * 3 + q];
                    acc.x += v.x; acc.y += v.y; acc.z += v.z; acc.w += v.w;
                }
                A[s][4 * q + 0] = acc.x; A[s][4 * q + 1] = acc.y;
                A[s][4 * q + 2] = acc.z; A[s][4 * q + 3] = acc.w;
            }
        }
#pragma unroll
        for (int c = 0; c < 3;  c++) ls[c]      += fabsf(A[0][c] - A[1][c]);
#pragma unroll
        for (int c = 0; c < 6;  c++) ls[3 + c]  += fabsf(A[1][c] - A[2][c]);
#pragma unroll
        for (int c = 0; c < 9;  c++) ls[9 + c]  += fabsf(A[2][c] - A[3][c]);
#pragma unroll
        for (int c = 0; c < 12; c++) ls[18 + c] += fabsf(A[3][c] - A[4][c]);
    }
    __shared__ float red[30][8];
    int wid = tid >> 5, lane = tid & 31;
#pragma unroll
    for (int v = 0; v < 30; v++) {
        float s = warpSum(ls[v]);
        if (lane == 0) red[v][wid] = s;
    }
    __syncthreads();
    if (tid < 30) {
        float s = 0.f;
#pragma unroll
        for (int w = 0; w < 8; w++) s += red[tid][w];
        int b = p >> 2, k = p & 3;
        out[b * 192 + k * 48 + 18 + tid] = s * (1.f / 2048.f);
    }
}

// ---------------- launch ----------------
extern "C" void kernel_launch(void* const* d_in, const int* in_sizes, int n_in,
                              void* d_out, int out_size) {
    (void)in_sizes; (void)n_in; (void)out_size;
    const float* pc = (const float*)d_in[0];   // [4,2048,3]
    const float* al = (const float*)d_in[1];   // [4,3]
    float* out = (float*)d_out;                // [768]

    prepK<<<(NP * N + 255) / 256, 256>>>(pc, al);
    degK<<<NP * N / 8, 256>>>();
    buildK<<<dim3(N / 256, N / 8, NP), 256>>>();

    for (int s = 1; s <= 16; s++)
        apply1K<<<dim3(4, JC1, NP), 256>>>(s - 1, s);

    midK<<<NP, 256>>>(out);

    for (int s = 1; s <= 16; s++)
        apply2K<<<dim3(4, JC2, NP), 256>>>(s - 1, s);

    finalK<<<NP, 256>>>(out);
}